// round 14
// baseline (speedup 1.0000x reference)
#include <cuda_runtime.h>

// out[b, q] = cos(x[b, q] + w[q]),  x: [4194304, 24] f32, w: [24] f32.
// Converged schedule: U=3 front-batched LDG.256 (96B in flight/thread,
// natural 40 regs — any launch-bounds cap below this breaks ptxas's
// batched schedule and regresses; caps above it are safe). v8 index i
// uses weight octet (i % 3); THREADS=288 divisible by 3 and per-block
// offset (864*bid) divisible by 3 => octet index is the loop-invariant
// (tid % 3). lb(288,5) = 45-reg cap (>40 natural), 45 warps/SM
// theoretical — highest residency compatible with the proven schedule.

#define THREADS 288
#define U 3

__device__ __forceinline__ void ld_v8_cs(const float* p, float* v) {
    asm volatile("ld.global.cs.v8.f32 {%0,%1,%2,%3,%4,%5,%6,%7}, [%8];"
                 : "=f"(v[0]), "=f"(v[1]), "=f"(v[2]), "=f"(v[3]),
                   "=f"(v[4]), "=f"(v[5]), "=f"(v[6]), "=f"(v[7])
                 : "l"(p));
}

__device__ __forceinline__ void st_v8_cs(float* p, const float* v) {
    asm volatile("st.global.cs.v8.f32 [%0], {%1,%2,%3,%4,%5,%6,%7,%8};"
                 :: "l"(p),
                    "f"(v[0]), "f"(v[1]), "f"(v[2]), "f"(v[3]),
                    "f"(v[4]), "f"(v[5]), "f"(v[6]), "f"(v[7])
                 : "memory");
}

__global__ __launch_bounds__(THREADS, 5)
void qfl_cos_kernel(const float* __restrict__ x,
                    const float* __restrict__ w,
                    float* __restrict__ out,
                    int n8) {
    int tid   = threadIdx.x;
    int base8 = blockIdx.x * (THREADS * U) + tid;

    // Loop-invariant weight octet: w[(tid%3)*8 .. +8)
    const float* wp = w + (tid % 3) * 8;
    float W[8];
#pragma unroll
    for (int j = 0; j < 8; j++) W[j] = __ldg(wp + j);

    if (base8 + (U - 1) * THREADS < n8) {
        float v[U][8];
#pragma unroll
        for (int k = 0; k < U; k++)
            ld_v8_cs(x + (size_t)(base8 + k * THREADS) * 8, v[k]);

#pragma unroll
        for (int k = 0; k < U; k++) {
            float r[8];
#pragma unroll
            for (int j = 0; j < 8; j++)
                r[j] = __cosf(v[k][j] + W[j]);
            st_v8_cs(out + (size_t)(base8 + k * THREADS) * 8, r);
        }
    } else {
        // Tail: last block only (12582912 % 864 != 0).
#pragma unroll
        for (int k = 0; k < U; k++) {
            int i = base8 + k * THREADS;
            if (i < n8) {
                float v[8], r[8];
                ld_v8_cs(x + (size_t)i * 8, v);
#pragma unroll
                for (int j = 0; j < 8; j++)
                    r[j] = __cosf(v[j] + W[j]);
                st_v8_cs(out + (size_t)i * 8, r);
            }
        }
    }
}

extern "C" void kernel_launch(void* const* d_in, const int* in_sizes, int n_in,
                              void* d_out, int out_size) {
    const float* x = (const float*)d_in[0];
    const float* w = (const float*)d_in[1];
    float* out = (float*)d_out;

    int n  = in_sizes[0];   // 100663296
    int n8 = n >> 3;        // 12582912 v8s

    int per_block = THREADS * U;     // 864
    int blocks = (n8 + per_block - 1) / per_block;   // 14564
    qfl_cos_kernel<<<blocks, THREADS>>>(x, w, out, n8);
}

// round 15
// speedup vs baseline: 1.0054x; 1.0054x over previous
#include <cuda_runtime.h>

// out[b, q] = cos(x[b, q] + w[q]),  x: [4194304, 24] f32, w: [24] f32.
// Converged schedule: U=3 front-batched LDG.256 (96B in flight/thread,
// natural 40 regs; caps below natural break ptxas's batched schedule).
// v8 index i uses weight octet (i % 3); THREADS=240 divisible by 3 and
// per-block offset (720*bid) divisible by 3 => octet index is the
// loop-invariant (tid % 3). lb(240,6) = 45-reg cap (>40 natural),
// 45 warps/SM theoretical with fine-grained CTAs for wave packing.

#define THREADS 240
#define U 3

__device__ __forceinline__ void ld_v8_cs(const float* p, float* v) {
    asm volatile("ld.global.cs.v8.f32 {%0,%1,%2,%3,%4,%5,%6,%7}, [%8];"
                 : "=f"(v[0]), "=f"(v[1]), "=f"(v[2]), "=f"(v[3]),
                   "=f"(v[4]), "=f"(v[5]), "=f"(v[6]), "=f"(v[7])
                 : "l"(p));
}

__device__ __forceinline__ void st_v8_cs(float* p, const float* v) {
    asm volatile("st.global.cs.v8.f32 [%0], {%1,%2,%3,%4,%5,%6,%7,%8};"
                 :: "l"(p),
                    "f"(v[0]), "f"(v[1]), "f"(v[2]), "f"(v[3]),
                    "f"(v[4]), "f"(v[5]), "f"(v[6]), "f"(v[7])
                 : "memory");
}

__global__ __launch_bounds__(THREADS, 6)
void qfl_cos_kernel(const float* __restrict__ x,
                    const float* __restrict__ w,
                    float* __restrict__ out,
                    int n8) {
    int tid   = threadIdx.x;
    int base8 = blockIdx.x * (THREADS * U) + tid;

    // Loop-invariant weight octet: w[(tid%3)*8 .. +8)
    const float* wp = w + (tid % 3) * 8;
    float W[8];
#pragma unroll
    for (int j = 0; j < 8; j++) W[j] = __ldg(wp + j);

    if (base8 + (U - 1) * THREADS < n8) {
        float v[U][8];
#pragma unroll
        for (int k = 0; k < U; k++)
            ld_v8_cs(x + (size_t)(base8 + k * THREADS) * 8, v[k]);

#pragma unroll
        for (int k = 0; k < U; k++) {
            float r[8];
#pragma unroll
            for (int j = 0; j < 8; j++)
                r[j] = __cosf(v[k][j] + W[j]);
            st_v8_cs(out + (size_t)(base8 + k * THREADS) * 8, r);
        }
    } else {
        // Tail: last block only (12582912 % 720 != 0).
#pragma unroll
        for (int k = 0; k < U; k++) {
            int i = base8 + k * THREADS;
            if (i < n8) {
                float v[8], r[8];
                ld_v8_cs(x + (size_t)i * 8, v);
#pragma unroll
                for (int j = 0; j < 8; j++)
                    r[j] = __cosf(v[j] + W[j]);
                st_v8_cs(out + (size_t)i * 8, r);
            }
        }
    }
}

extern "C" void kernel_launch(void* const* d_in, const int* in_sizes, int n_in,
                              void* d_out, int out_size) {
    const float* x = (const float*)d_in[0];
    const float* w = (const float*)d_in[1];
    float* out = (float*)d_out;

    int n  = in_sizes[0];   // 100663296
    int n8 = n >> 3;        // 12582912 v8s

    int per_block = THREADS * U;     // 720
    int blocks = (n8 + per_block - 1) / per_block;   // 17477
    qfl_cos_kernel<<<blocks, THREADS>>>(x, w, out, n8);
}